// round 16
// baseline (speedup 1.0000x reference)
#include <cuda_runtime.h>
#include <cuda_fp16.h>
#include <cstdint>

#define OUTD 11008
#define IND  4096
#define GCNT 704512
#define CDIM 172
#define NB   8
#define CHUNK 512

typedef unsigned int u32;

// smem layout (bytes). A rows: 0..31 = 16*hi_nibble, 32..63 = lo_nibble.
// Row stride 268 words (536 halfs): 268 mod 32 = 12 -> fragment LDS pattern
// (l>>2)*12 + (l&3) is a perfect 32-bank permutation (conflict-free).
#define AW_STRIDE 268
#define A_OFF   0
#define A_BYTES (64 * AW_STRIDE * 4)          /* 68608 */
#define YHI_OFF A_BYTES
#define Y_BYTES (NB * AW_STRIDE * 4)          /* 8576 */
#define YLO_OFF (YHI_OFF + Y_BYTES)
#define TZ_OFF  (YLO_OFF + Y_BYTES)
#define SMEM_BYTES (TZ_OFF + 64)              /* 85824 */

// ---------------------------------------------------------------------------
__global__ void init_out_kernel(const float* __restrict__ bias,
                                float* __restrict__ out) {
    int idx = blockIdx.x * blockDim.x + threadIdx.x;
    if (idx < NB * OUTD) out[idx] = bias[idx % OUTD];
}

// ---------------------------------------------------------------------------
__device__ __forceinline__ u32 nib2h(u32 v) {      // f16x2: v - {1024,1024}
    u32 r;
    asm("sub.rn.f16x2 %0, %1, %2;" : "=r"(r) : "r"(v), "r"(0x64006400u));
    return r;
}
__device__ __forceinline__ void mma16816(float* c, u32 a0, u32 a1, u32 a2,
                                         u32 a3, u32 b0, u32 b1) {
    asm volatile(
        "mma.sync.aligned.m16n8k16.row.col.f32.f16.f16.f32 "
        "{%0,%1,%2,%3}, {%4,%5,%6,%7}, {%8,%9}, {%0,%1,%2,%3};"
        : "+f"(c[0]), "+f"(c[1]), "+f"(c[2]), "+f"(c[3])
        : "r"(a0), "r"(a1), "r"(a2), "r"(a3), "r"(b0), "r"(b1));
}

// ---------------------------------------------------------------------------
// Block = (c, chunk of 512 k). GEMM: C[64 rows][8 batches] += A[64][512]*B.
// A = exact fp16 nibbles (hi rows pre-scaled x16, fixed in epilogue).
// B = y_hi + y_lo fp16 split of y = s*x; fp32 accumulation via HMMA.
// Warp w: stages batch w of y (+T term), then owns k-slice [64w, 64w+64).
// ---------------------------------------------------------------------------
__global__ __launch_bounds__(256) void hqq_mma_kernel(
    const int*   __restrict__ Wq,     // [32, 704512] int32 (one byte per elem)
    const float* __restrict__ scale,  // [704512]
    const float* __restrict__ zero,   // [704512]
    const float* __restrict__ x,      // [8, 4096]
    float*       __restrict__ out)    // [8, 11008]
{
    extern __shared__ __align__(16) char sm[];
    u32*   Aw  = reinterpret_cast<u32*>(sm + A_OFF);
    half*  Yh  = reinterpret_cast<half*>(sm + YHI_OFF);
    half*  Yl  = reinterpret_cast<half*>(sm + YLO_OFF);
    float* Tz  = reinterpret_cast<float*>(sm + TZ_OFF);

    const int tid = threadIdx.x;
    const int h   = blockIdx.x & 7;                 // k-chunk
    const int c   = blockIdx.x >> 3;                // 0..171
    const int ib  = h * CHUNK;
    const int cbase = c * IND + ib;

    const int w = tid >> 5;                         // warp 0..7
    const int l = tid & 31;

    // ---- stage y (warp w = batch w) + chunk-partial T -------------------
    {
        const float* xb = x + w * IND + ib;
        float tz = 0.f;
        #pragma unroll
        for (int r = 0; r < 16; ++r) {
            const int k  = l + (r << 5);
            const int gi = cbase + k;
            const float sv = __ldg(scale + gi);
            const float zv = __ldg(zero + gi);
            const float y  = __ldg(xb + k) * sv;
            const half hh  = __float2half_rn(y);
            const half hl  = __float2half_rn(y - __half2float(hh));
            Yh[w * (AW_STRIDE * 2) + k] = hh;
            Yl[w * (AW_STRIDE * 2) + k] = hl;
            tz = fmaf(zv, y, tz);
        }
        #pragma unroll
        for (int d = 16; d >= 1; d >>= 1)
            tz += __shfl_xor_sync(0xffffffffu, tz, d);
        if (l == 0) Tz[w] = tz;
    }

    // ---- stage A: Wq bytes -> exact fp16 nibbles ------------------------
    #pragma unroll
    for (int it = 0; it < 16; ++it) {
        const int idx = tid + (it << 8);            // 0..4095 int4's
        const int row = idx >> 7;                   // Wq row 0..31
        const int i4  = idx & 127;
        const int4 q = __ldg(
            reinterpret_cast<const int4*>(Wq + (long)row * GCNT + cbase) + i4);
        const u32 m1 = __byte_perm((u32)q.x, (u32)q.y, 0x5410);
        const u32 m2 = __byte_perm((u32)q.z, (u32)q.w, 0x5410);
        const u32 h1 = nib2h((m1 & 0x00F000F0u) | 0x64006400u); // {16nh,16nh}
        const u32 h2 = nib2h((m2 & 0x00F000F0u) | 0x64006400u);
        const u32 lo1 = nib2h((m1 & 0x000F000Fu) | 0x64006400u); // {nl,nl}
        const u32 lo2 = nib2h((m2 & 0x000F000Fu) | 0x64006400u);
        const int wd = row * AW_STRIDE + 2 * i4;
        *reinterpret_cast<uint2*>(Aw + wd) = make_uint2(h1, h2);
        *reinterpret_cast<uint2*>(Aw + wd + 32 * AW_STRIDE) = make_uint2(lo1, lo2);
    }
    __syncthreads();

    // ---- MMA main loop: warp w covers k in [64w, 64w+64) ----------------
    float C[4][4];
    #pragma unroll
    for (int m = 0; m < 4; ++m)
        #pragma unroll
        for (int j = 0; j < 4; ++j) C[m][j] = 0.f;

    const int r0 = l >> 2;
    const u32* Yhw = reinterpret_cast<const u32*>(Yh);
    const u32* Ylw = reinterpret_cast<const u32*>(Yl);

    #pragma unroll
    for (int kk = 0; kk < 4; ++kk) {
        const int acol = (w << 5) + (kk << 3) + (l & 3);  // word offset in row

        u32 a[4][4];
        #pragma unroll
        for (int m = 0; m < 4; ++m) {
            const int rowb = (m << 4) + r0;
            a[m][0] = Aw[rowb * AW_STRIDE + acol];
            a[m][1] = Aw[(rowb + 8) * AW_STRIDE + acol];
            a[m][2] = Aw[rowb * AW_STRIDE + acol + 4];
            a[m][3] = Aw[(rowb + 8) * AW_STRIDE + acol + 4];
        }
        const int yb = r0 * AW_STRIDE + acol;       // batch = l>>2
        const u32 bh0 = Yhw[yb], bh1 = Yhw[yb + 4];
        const u32 bl0 = Ylw[yb], bl1 = Ylw[yb + 4];

        #pragma unroll
        for (int m = 0; m < 4; ++m) {
            mma16816(C[m], a[m][0], a[m][1], a[m][2], a[m][3], bh0, bh1);
            mma16816(C[m], a[m][0], a[m][1], a[m][2], a[m][3], bl0, bl1);
        }
    }

    // ---- cross-warp reduce (overlay y region) + epilogue ----------------
    __syncthreads();                                // all MMA reads done
    float* red = reinterpret_cast<float*>(sm + YHI_OFF);  // 8*512 floats
    #pragma unroll
    for (int m = 0; m < 4; ++m)
        #pragma unroll
        for (int j = 0; j < 4; ++j) {
            const int row = (m << 4) + r0 + ((j >> 1) << 3);
            const int bc  = ((l & 3) << 1) + (j & 1);
            red[(w << 9) + (row << 3) + bc] = C[m][j];
        }
    __syncthreads();

    for (int e = tid; e < 512; e += 256) {
        float s = 0.f;
        #pragma unroll
        for (int ww = 0; ww < 8; ++ww) s += red[(ww << 9) + e];
        const int row = e >> 3, b = e & 7;
        if (row < 32) s *= 0.0625f;                 // undo x16 of hi nibbles
        s -= Tz[b];                                 // chunk zero-point term
        atomicAdd(out + b * OUTD + row * CDIM + c, s);
    }
}

// ---------------------------------------------------------------------------
extern "C" void kernel_launch(void* const* d_in, const int* in_sizes, int n_in,
                              void* d_out, int out_size) {
    const int*   Wq    = (const int*)  d_in[0];
    const float* scale = (const float*)d_in[1];
    const float* zero  = (const float*)d_in[2];
    const float* x     = (const float*)d_in[3];
    const float* bias  = (const float*)d_in[4];
    float* out = (float*)d_out;

    cudaFuncSetAttribute(hqq_mma_kernel,
                         cudaFuncAttributeMaxDynamicSharedMemorySize,
                         SMEM_BYTES);
    init_out_kernel<<<(NB * OUTD + 255) / 256, 256>>>(bias, out);
    hqq_mma_kernel<<<CDIM * (IND / CHUNK), 256, SMEM_BYTES>>>(
        Wq, scale, zero, x, out);
}

// round 17
// speedup vs baseline: 1.2810x; 1.2810x over previous
#include <cuda_runtime.h>
#include <cuda_fp16.h>
#include <cstdint>

#define OUTD 11008
#define IND  4096
#define GCNT 704512
#define CDIM 172
#define NB   8
#define CHUNK 256

typedef unsigned int u32;

// A rows: 0..31 = 16*hi_nibble, 32..63 = lo_nibble. Row stride 132 words:
// 132 mod 32 = 4 -> fragment LDS bank = r0*4 + (l&3) + const: perfect
// 32-bank permutation; +8-row offset (8*132 = 1056 = 33*32) is bank-neutral.
#define AWS 132
#define A_WORDS   (64 * AWS)          /* 8448  */
#define YH_WORDS  (NB * AWS)          /* 1056  */
#define YL_WORDS  (NB * AWS)
#define SM_WORDS  (A_WORDS + YH_WORDS + YL_WORDS + 8)  /* 10568 = 42272 B */

// ---------------------------------------------------------------------------
__global__ void init_out_kernel(const float* __restrict__ bias,
                                float* __restrict__ out) {
    int idx = blockIdx.x * blockDim.x + threadIdx.x;
    if (idx < NB * OUTD) out[idx] = bias[idx % OUTD];
}

// ---------------------------------------------------------------------------
__device__ __forceinline__ u32 nib2h(u32 v) {      // f16x2: v - {1024,1024}
    u32 r;
    asm("sub.rn.f16x2 %0, %1, %2;" : "=r"(r) : "r"(v), "r"(0x64006400u));
    return r;
}
__device__ __forceinline__ void mma16816(float* c, u32 a0, u32 a1, u32 a2,
                                         u32 a3, u32 b0, u32 b1) {
    asm volatile(
        "mma.sync.aligned.m16n8k16.row.col.f32.f16.f16.f32 "
        "{%0,%1,%2,%3}, {%4,%5,%6,%7}, {%8,%9}, {%0,%1,%2,%3};"
        : "+f"(c[0]), "+f"(c[1]), "+f"(c[2]), "+f"(c[3])
        : "r"(a0), "r"(a1), "r"(a2), "r"(a3), "r"(b0), "r"(b1));
}

// ---------------------------------------------------------------------------
// Block = (c, chunk of 256 k). GEMM: C[64 rows][8 batches] += A[64][256]*B.
// A = exact fp16 nibbles (hi rows x16, fixed in epilogue). B = y_hi + y_lo
// fp16 split of y = s*x; fp32 accumulation via HMMA. Warp w: stages batch w
// of y (+T term), then owns k-slice [32w, 32w+32).
// ---------------------------------------------------------------------------
__global__ __launch_bounds__(256, 4) void hqq_mma_kernel(
    const int*   __restrict__ Wq,     // [32, 704512] int32 (one byte per elem)
    const float* __restrict__ scale,  // [704512]
    const float* __restrict__ zero,   // [704512]
    const float* __restrict__ x,      // [8, 4096]
    float*       __restrict__ out)    // [8, 11008]
{
    __shared__ __align__(16) u32 smw[SM_WORDS];
    u32*   Aw = smw;
    half*  Yh = reinterpret_cast<half*>(smw + A_WORDS);
    half*  Yl = reinterpret_cast<half*>(smw + A_WORDS + YH_WORDS);
    float* Tz = reinterpret_cast<float*>(smw + A_WORDS + YH_WORDS + YL_WORDS);

    const int tid = threadIdx.x;
    const int h   = blockIdx.x & 15;                // k-chunk 0..15
    const int c   = blockIdx.x >> 4;                // 0..171
    const int ib  = h * CHUNK;
    const int cbase = c * IND + ib;

    const int w = tid >> 5;                         // warp 0..7
    const int l = tid & 31;

    // ---- stage y (warp w = batch w) + chunk-partial T -------------------
    {
        const float* xb = x + w * IND + ib;
        float tz = 0.f;
        #pragma unroll
        for (int r = 0; r < 8; ++r) {
            const int k  = l + (r << 5);
            const int gi = cbase + k;
            const float sv = __ldg(scale + gi);
            const float zv = __ldg(zero + gi);
            const float y  = __ldg(xb + k) * sv;
            const half hh  = __float2half_rn(y);
            const half hl  = __float2half_rn(y - __half2float(hh));
            Yh[w * (AWS * 2) + k] = hh;
            Yl[w * (AWS * 2) + k] = hl;
            tz = fmaf(zv, y, tz);
        }
        #pragma unroll
        for (int d = 16; d >= 1; d >>= 1)
            tz += __shfl_xor_sync(0xffffffffu, tz, d);
        if (l == 0) Tz[w] = tz;
    }

    // ---- stage A: Wq bytes -> exact fp16 nibbles ------------------------
    #pragma unroll
    for (int it = 0; it < 8; ++it) {
        const int idx = tid + (it << 8);            // 0..2047 int4's
        const int row = idx >> 6;                   // Wq row 0..31
        const int i4  = idx & 63;
        const int4 q = __ldg(
            reinterpret_cast<const int4*>(Wq + (long)row * GCNT + cbase) + i4);
        const u32 m1 = __byte_perm((u32)q.x, (u32)q.y, 0x5410);
        const u32 m2 = __byte_perm((u32)q.z, (u32)q.w, 0x5410);
        const u32 h1 = nib2h((m1 & 0x00F000F0u) | 0x64006400u); // {16nh,16nh}
        const u32 h2 = nib2h((m2 & 0x00F000F0u) | 0x64006400u);
        const u32 o1 = nib2h((m1 & 0x000F000Fu) | 0x64006400u); // {nl,nl}
        const u32 o2 = nib2h((m2 & 0x000F000Fu) | 0x64006400u);
        const int wd = row * AWS + 2 * i4;
        *reinterpret_cast<uint2*>(Aw + wd) = make_uint2(h1, h2);
        *reinterpret_cast<uint2*>(Aw + wd + 32 * AWS) = make_uint2(o1, o2);
    }
    __syncthreads();

    // ---- MMA main loop: warp w covers k in [32w, 32w+32) ----------------
    float C[4][4];
    #pragma unroll
    for (int m = 0; m < 4; ++m)
        #pragma unroll
        for (int j = 0; j < 4; ++j) C[m][j] = 0.f;

    const int r0 = l >> 2;
    const u32* Yhw = reinterpret_cast<const u32*>(Yh);
    const u32* Ylw = reinterpret_cast<const u32*>(Yl);

    #pragma unroll
    for (int kk = 0; kk < 2; ++kk) {
        const int acol = (w << 4) + (kk << 3) + (l & 3);  // word offset in row

        u32 a[4][4];
        #pragma unroll
        for (int m = 0; m < 4; ++m) {
            const int rowb = (m << 4) + r0;
            a[m][0] = Aw[rowb * AWS + acol];
            a[m][1] = Aw[(rowb + 8) * AWS + acol];
            a[m][2] = Aw[rowb * AWS + acol + 4];
            a[m][3] = Aw[(rowb + 8) * AWS + acol + 4];
        }
        const int yb = r0 * AWS + acol;             // batch = l>>2
        const u32 bh0 = Yhw[yb], bh1 = Yhw[yb + 4];
        const u32 bl0 = Ylw[yb], bl1 = Ylw[yb + 4];

        #pragma unroll
        for (int m = 0; m < 4; ++m) {
            mma16816(C[m], a[m][0], a[m][1], a[m][2], a[m][3], bh0, bh1);
            mma16816(C[m], a[m][0], a[m][1], a[m][2], a[m][3], bl0, bl1);
        }
    }

    // ---- cross-warp reduce (overlay A region) + epilogue ----------------
    __syncthreads();                                // all MMA reads done
    float* red = reinterpret_cast<float*>(smw);     // 8 warps x 512 floats
    #pragma unroll
    for (int m = 0; m < 4; ++m)
        #pragma unroll
        for (int j = 0; j < 4; ++j) {
            const int row = (m << 4) + r0 + ((j >> 1) << 3);
            const int bc  = ((l & 3) << 1) + (j & 1);
            red[(w << 9) + (row << 3) + bc] = C[m][j];
        }
    __syncthreads();

    for (int e = tid; e < 512; e += 256) {
        float s = 0.f;
        #pragma unroll
        for (int ww = 0; ww < 8; ++ww) s += red[(ww << 9) + e];
        const int row = e >> 3, b = e & 7;
        if (row < 32) s *= 0.0625f;                 // undo x16 of hi nibbles
        s -= Tz[b];                                 // chunk zero-point term
        atomicAdd(out + b * OUTD + row * CDIM + c, s);
    }
}

// ---------------------------------------------------------------------------
extern "C" void kernel_launch(void* const* d_in, const int* in_sizes, int n_in,
                              void* d_out, int out_size) {
    const int*   Wq    = (const int*)  d_in[0];
    const float* scale = (const float*)d_in[1];
    const float* zero  = (const float*)d_in[2];
    const float* x     = (const float*)d_in[3];
    const float* bias  = (const float*)d_in[4];
    float* out = (float*)d_out;

    init_out_kernel<<<(NB * OUTD + 255) / 256, 256>>>(bias, out);
    hqq_mma_kernel<<<CDIM * (IND / CHUNK), 256>>>(Wq, scale, zero, x, out);
}